// round 10
// baseline (speedup 1.0000x reference)
#include <cuda_runtime.h>
#include <cuda_fp16.h>
#include <math.h>
#include <stdint.h>

// ---------------------------------------------------------------------------
// ReDrafterHead: 2-layer GRU draft head + big vocab projection.
// B=64, HIDDEN=4096, DH=512, VOCAB=50257, NUM_DRAFT=4.
//
// Round 10:
//  - gru: 512 threads, double-buffered smem (1 sync/k-tile), utile 1x3,
//    epi aliases W buffer.
//  - logits: CTA 128x128, warp 64x32, single fp16 term, 2 CTAs/SM.
// ---------------------------------------------------------------------------

#define B_      64
#define HID     4096
#define DH      512
#define VOCAB   50257
#define NDRAFT  4
#define GRIDN   128

__device__ float g_h[2][2][B_ * DH];        // [layer][slot][b*DH+j]
__device__ float g_part[16 * B_ * DH];      // ip split-K partials
__device__ __half g_Ah[B_ * NDRAFT * DH];   // h2 rows fp16, m = b*4+step
__device__ unsigned int g_bcount;           // monotonic barrier counter

__device__ __forceinline__ float sigmoidf_(float v) { return 1.0f / (1.0f + __expf(-v)); }

__device__ __forceinline__ uint32_t pack_f16x2(__half lo, __half hi) {
    return ((uint32_t)__half_as_ushort(hi) << 16) | (uint32_t)__half_as_ushort(lo);
}
__device__ __forceinline__ uint32_t smem_to_u32(const void* p) {
    uint32_t a;
    asm("{ .reg .u64 t; cvta.to.shared.u64 t, %1; cvt.u32.u64 %0, t; }" : "=r"(a) : "l"(p));
    return a;
}
__device__ __forceinline__ void ldsm4(uint32_t* r, uint32_t addr) {
    asm volatile("ldmatrix.sync.aligned.m8n8.x4.shared.b16 {%0,%1,%2,%3}, [%4];"
        : "=r"(r[0]), "=r"(r[1]), "=r"(r[2]), "=r"(r[3]) : "r"(addr));
}
__device__ __forceinline__ void mma16816h(float* d, const uint32_t* a, const uint32_t* b) {
    asm volatile("mma.sync.aligned.m16n8k16.row.col.f32.f16.f16.f32 "
        "{%0,%1,%2,%3}, {%4,%5,%6,%7}, {%8,%9}, {%0,%1,%2,%3};"
        : "+f"(d[0]), "+f"(d[1]), "+f"(d[2]), "+f"(d[3])
        : "r"(a[0]), "r"(a[1]), "r"(a[2]), "r"(a[3]), "r"(b[0]), "r"(b[1]));
}

// Grid-wide barrier: monotonic counter (graph-replay safe; GRIDN co-resident).
__device__ __forceinline__ void grid_barrier(int tid) {
    __syncthreads();
    if (tid == 0) {
        __threadfence();
        unsigned int old = atomicAdd(&g_bcount, 1u);
        unsigned int target = (old / GRIDN + 1u) * GRIDN;
        unsigned int v;
        do {
            asm volatile("ld.acquire.gpu.global.u32 %0, [%1];" : "=r"(v) : "l"(&g_bcount));
        } while (v < target);
    }
    __syncthreads();
}

// ---------------------------------------------------------------------------
struct SmemIP { float As[32][64]; float Ws[32][64]; };
// Double-buffered GRU stage. A2 base offset ≡ A1 + 4 floats (mod 32 banks)
// -> disjoint bank sets in the mixed A1/A2 load. epi aliases W (used only
// after the final k-tile sync).
struct SmemG {
    float A1[2][64][36];
    float padA[4];
    float A2[2][64][36];
    union { float W[2][24][36]; float epi[64][27]; } u;
};

// One GRU layer for one step, 512 threads. CTA owns j-range [jb, jb+4):
// GEMM 64 x 24 x 512 (cols 0-11: gi {r,z,n}x4j via Wih & A1; 12-23: gh via
// Whh & A2) + fused combine. a1mode: 0 = zeros, 1 = embed gather, 2 = ptr.
__device__ __forceinline__ void gates_layer(
    SmemG& s, const int* sTid, int tid, int jb,
    int a1mode, const float* A1g, const float* A2g, const float* embed,
    const float* Wih, const float* Whh,
    const float* bih, const float* bhh,
    const float* hOld, float* hNew,
    bool writeA, int step)
{
    const int mg = tid >> 3;               // 0..63 (one row)
    const int g  = tid & 7;                // 0..7
    const int c0 = g * 3;                  // 0..21
    const bool useA1 = (g < 4);
    float acc[3] = {};

    // loader indices: one float4 per array per tile per thread
    const int frow = tid >> 3;             // 0..63
    const int fc4  = (tid & 7) * 4;        // 0..28
    const int wr   = tid >> 3;             // 0..23 valid when tid < 192
    const int wrr  = (wr < 12) ? wr : wr - 12;
    const float* wbase = (wr < 12) ? Wih : Whh;
    const long  woff = (long)((wrr >> 2) * 512 + jb + (wrr & 3)) * DH + fc4;

    float4 pA1, pA2, pW;
    auto fetch = [&](int kt) {
        if (a1mode == 0)      pA1 = make_float4(0.f, 0.f, 0.f, 0.f);
        else if (a1mode == 1) pA1 = *reinterpret_cast<const float4*>(
                                      &embed[(long)sTid[frow] * DH + kt + fc4]);
        else                  pA1 = *reinterpret_cast<const float4*>(
                                      &A1g[frow * DH + kt + fc4]);
        pA2 = *reinterpret_cast<const float4*>(&A2g[frow * DH + kt + fc4]);
        if (tid < 192)
            pW = *reinterpret_cast<const float4*>(&wbase[woff + kt]);
    };
    auto stage = [&](int st) {
        *reinterpret_cast<float4*>(&s.A1[st][frow][fc4]) = pA1;
        *reinterpret_cast<float4*>(&s.A2[st][frow][fc4]) = pA2;
        if (tid < 192)
            *reinterpret_cast<float4*>(&s.u.W[st][wr][fc4]) = pW;
    };

    fetch(0);
    stage(0);
    __syncthreads();

    #pragma unroll 1
    for (int t = 0; t < 16; t++) {
        const int st = t & 1;
        if (t + 1 < 16) fetch((t + 1) * 32);     // LDGs issued, hidden by FMA
        const float* As = useA1 ? &s.A1[st][0][0] : &s.A2[st][0][0];
        const float* Wp = &s.u.W[st][0][0];
        #pragma unroll
        for (int k = 0; k < 32; k += 4) {
            float4 w0 = *reinterpret_cast<const float4*>(&Wp[(c0 + 0) * 36 + k]);
            float4 w1 = *reinterpret_cast<const float4*>(&Wp[(c0 + 1) * 36 + k]);
            float4 w2 = *reinterpret_cast<const float4*>(&Wp[(c0 + 2) * 36 + k]);
            float4 a  = *reinterpret_cast<const float4*>(&As[mg * 36 + k]);
            acc[0] += a.x * w0.x + a.y * w0.y + a.z * w0.z + a.w * w0.w;
            acc[1] += a.x * w1.x + a.y * w1.y + a.z * w1.z + a.w * w1.w;
            acc[2] += a.x * w2.x + a.y * w2.y + a.z * w2.z + a.w * w2.w;
        }
        if (t + 1 < 16) stage(1 - st);
        __syncthreads();
    }

    // epi aliases W; all compute done (loop ends with sync)
    #pragma unroll
    for (int cc = 0; cc < 3; cc++)
        s.u.epi[mg][c0 + cc] = acc[cc];
    __syncthreads();
    if (tid < 256) {
        int m = tid >> 2, j = tid & 3, jj = jb + j;
        const float* E = &s.u.epi[m][0];
        float r = sigmoidf_(E[j]       + bih[jj]        + E[12 + j] + bhh[jj]);
        float z = sigmoidf_(E[4 + j]   + bih[512 + jj]  + E[16 + j] + bhh[512 + jj]);
        float n = tanhf(E[8 + j] + bih[1024 + jj] + r * (E[20 + j] + bhh[1024 + jj]));
        float hnew = (1.f - z) * n + z * hOld[m * DH + jj];
        hNew[m * DH + jj] = hnew;
        if (writeA)
            g_Ah[(m * NDRAFT + step) * DH + jj] = __float2half(hnew);
    }
}

// NOTE: epi column layout differs from round 9: thread (mg,g) writes cols
// c0..c0+2 where cols 0-11 are gi over (gate-major j-blocks? no) — mapping:
// col cx (0..11) corresponds to W row cx: gate (cx>>2), j (cx&3). So
// E[gate*4 + j] for gi and E[12 + gate*4 + j] for gh. Used above.

// ---------------------------------------------------------------------------
__global__ __launch_bounds__(512) void gru_fused(
    const float* __restrict__ hidden, const int* __restrict__ tids,
    const float* __restrict__ ip_w,  const float* __restrict__ ip_b,
    const float* __restrict__ w_ih0, const float* __restrict__ w_hh0,
    const float* __restrict__ b_ih0, const float* __restrict__ b_hh0,
    const float* __restrict__ w_ih1, const float* __restrict__ w_hh1,
    const float* __restrict__ b_ih1, const float* __restrict__ b_hh1,
    const float* __restrict__ embed)
{
    __shared__ union { SmemIP ip; SmemG g; } sm;
    __shared__ int sTid[64];
    const int tid = threadIdx.x;
    const int c = blockIdx.x;

    // ---- phase 0: input projection partials (64x64 n-tile, 256-k slice) ----
    {
        const int n0 = (c & 7) * 64;
        const int kbase = (c >> 3) * 256;
        const int ty = tid >> 4, tx = tid & 15;     // compute: tid < 256
        float acc[4][4] = {};
        for (int kt = 0; kt < 256; kt += 32) {
            {
                int f = tid;                         // 512 loaders
                int m = f >> 3;
                int kq = (f & 7) << 2;
                float4 va = *reinterpret_cast<const float4*>(&hidden[m * HID + kbase + kt + kq]);
                sm.ip.As[kq + 0][m] = va.x; sm.ip.As[kq + 1][m] = va.y;
                sm.ip.As[kq + 2][m] = va.z; sm.ip.As[kq + 3][m] = va.w;
                float4 vw = *reinterpret_cast<const float4*>(&ip_w[(n0 + m) * HID + kbase + kt + kq]);
                sm.ip.Ws[kq + 0][m] = vw.x; sm.ip.Ws[kq + 1][m] = vw.y;
                sm.ip.Ws[kq + 2][m] = vw.z; sm.ip.Ws[kq + 3][m] = vw.w;
            }
            __syncthreads();
            if (tid < 256) {
                #pragma unroll
                for (int kk = 0; kk < 32; kk++) {
                    float a[4], b[4];
                    #pragma unroll
                    for (int i = 0; i < 4; i++) { a[i] = sm.ip.As[kk][ty * 4 + i]; b[i] = sm.ip.Ws[kk][tx * 4 + i]; }
                    #pragma unroll
                    for (int i = 0; i < 4; i++)
                        #pragma unroll
                        for (int j = 0; j < 4; j++) acc[i][j] += a[i] * b[j];
                }
            }
            __syncthreads();
        }
        if (tid < 256) {
            float* part = g_part + (c >> 3) * (B_ * DH);
            #pragma unroll
            for (int i = 0; i < 4; i++)
                #pragma unroll
                for (int j = 0; j < 4; j++)
                    part[(ty * 4 + i) * DH + n0 + tx * 4 + j] = acc[i][j];
        }
    }
    grid_barrier(tid);

    // ---- phase 1: reduce 16 partials + bias ----
    if (tid < 256) {
        int idx = c * 256 + tid;
        float s = 0.f;
        #pragma unroll
        for (int p = 0; p < 16; p++) s += g_part[p * (B_ * DH) + idx];
        s += ip_b[idx & (DH - 1)];
        g_h[0][0][idx] = s;
        g_h[1][0][idx] = s;
    }
    grid_barrier(tid);

    // ---- 4 draft steps x 2 GRU layers ----
    const int jb = c * 4;
    for (int step = 0; step < NDRAFT; step++) {
        const int p = step & 1;
        if (step > 0 && tid < 64) sTid[tid] = tids[tid * NDRAFT + step - 1];
        __syncthreads();
        gates_layer(sm.g, sTid, tid, jb,
                    (step == 0) ? 0 : 1, nullptr, g_h[0][p], embed,
                    w_ih0, w_hh0, b_ih0, b_hh0,
                    g_h[0][p], g_h[0][1 - p], false, step);
        grid_barrier(tid);
        gates_layer(sm.g, sTid, tid, jb,
                    2, g_h[0][1 - p], g_h[1][p], embed,
                    w_ih1, w_hh1, b_ih1, b_hh1,
                    g_h[1][p], g_h[1][1 - p], true, step);
        grid_barrier(tid);
    }
}

// ---------------------------------------------------------------------------
// Logits GEMM via single fp16 mma.sync (fp32 accum).
// CTA tile 128(M) x 128(N) x 32(K); 8 warps (2 M x 4 N); warp tile 64x32.
// smem 40KB -> 2 CTAs/SM. grid (2, 393): m-half pairs share B via L2.
// ---------------------------------------------------------------------------
#define ROWB 80
#define AH_OFF(s) ((s) * 10240)
#define BH_OFF(s) (20480 + (s) * 10240)
#define LOGITS_SMEM 40960

__global__ __launch_bounds__(256, 2) void logits_mma(const float* __restrict__ W,
                                                     float* __restrict__ out)
{
    extern __shared__ char smem[];
    const uint32_t sbase = smem_to_u32(smem);
    const int tid  = threadIdx.x;
    const int lane = tid & 31;
    const int w    = tid >> 5;
    const int wm   = w >> 2;   // 0..1
    const int wn   = w & 3;    // 0..3
    const int m0   = blockIdx.x * 128;
    const int n0   = blockIdx.y * 128;

    float d[4][4][4];
    #pragma unroll
    for (int i = 0; i < 4; i++)
        #pragma unroll
        for (int j = 0; j < 4; j++)
            #pragma unroll
            for (int q = 0; q < 4; q++) d[i][j][q] = 0.f;

    float4 breg[4];

    auto cpasync_A = [&](int c, int s) {
        const int k0 = c * 32;
        #pragma unroll
        for (int i = 0; i < 2; i++) {
            int idx = tid + i * 256;         // 0..511
            int row = idx >> 2;              // 0..127
            int ch  = idx & 3;               // 16B chunk (8 halves)
            const __half* sh = &g_Ah[(m0 + row) * DH + k0 + ch * 8];
            uint32_t dh = sbase + AH_OFF(s) + row * ROWB + ch * 16;
            asm volatile("cp.async.ca.shared.global [%0], [%1], 16;" :: "r"(dh), "l"(sh));
        }
        asm volatile("cp.async.commit_group;" ::: "memory");
    };

    auto ldg_B = [&](int c) {
        const int k0 = c * 32;
        #pragma unroll
        for (int i = 0; i < 4; i++) {
            int idx = tid + i * 256;         // 0..1023
            int row = idx >> 3;              // 0..127
            int col = (idx & 7) * 4;
            int vr = n0 + row;
            breg[i] = (vr < VOCAB)
                ? *reinterpret_cast<const float4*>(&W[(long)vr * DH + k0 + col])
                : make_float4(0.f, 0.f, 0.f, 0.f);
        }
    };

    auto sts_B = [&](int s) {
        #pragma unroll
        for (int i = 0; i < 4; i++) {
            int idx = tid + i * 256;
            int row = idx >> 3;
            int col = (idx & 7) * 4;
            float4 v = breg[i];
            uint2 ph;
            ph.x = pack_f16x2(__float2half(v.x), __float2half(v.y));
            ph.y = pack_f16x2(__float2half(v.z), __float2half(v.w));
            *reinterpret_cast<uint2*>(smem + BH_OFF(s) + row * ROWB + col * 2) = ph;
        }
    };

    auto compute = [&](int s) {
        #pragma unroll
        for (int ks = 0; ks < 2; ks++) {
            uint32_t ah[4][4];
            #pragma unroll
            for (int mi = 0; mi < 4; mi++) {
                int row = wm * 64 + mi * 16 + (lane & 15);
                int kc  = ks * 32 + (lane >> 4) * 16;
                ldsm4(ah[mi], sbase + AH_OFF(s) + row * ROWB + kc);
            }
            uint32_t bh[4][2];
            #pragma unroll
            for (int nb = 0; nb < 2; nb++) {
                int gq  = lane >> 3;
                int row = wn * 32 + nb * 16 + (gq >> 1) * 8 + (lane & 7);
                int kc  = ks * 32 + (gq & 1) * 16;
                ldsm4(&bh[nb * 2][0], sbase + BH_OFF(s) + row * ROWB + kc);
            }
            #pragma unroll
            for (int mi = 0; mi < 4; mi++)
                #pragma unroll
                for (int ni = 0; ni < 4; ni++)
                    mma16816h(d[mi][ni], ah[mi], bh[ni]);
        }
    };

    cpasync_A(0, 0);
    ldg_B(0);
    sts_B(0);
    asm volatile("cp.async.wait_group 0;" ::: "memory");
    __syncthreads();

    #pragma unroll 1
    for (int c = 0; c < 16; c++) {
        int s = c & 1;
        if (c + 1 < 16) {
            cpasync_A(c + 1, 1 - s);
            ldg_B(c + 1);
        }
        compute(s);
        if (c + 1 < 16) {
            sts_B(1 - s);
            asm volatile("cp.async.wait_group 0;" ::: "memory");
        }
        __syncthreads();
    }

    const int g  = lane >> 2;
    const int i2 = (lane & 3) * 2;
    #pragma unroll
    for (int mi = 0; mi < 4; mi++) {
        int r0 = m0 + wm * 64 + mi * 16 + g;
        long rb0 = (long)r0 * VOCAB;
        long rb1 = (long)(r0 + 8) * VOCAB;
        #pragma unroll
        for (int ni = 0; ni < 4; ni++) {
            int col = n0 + wn * 32 + ni * 8 + i2;
            if (col < VOCAB) {
                out[rb0 + col] = d[mi][ni][0];
                out[rb1 + col] = d[mi][ni][2];
                if (col + 1 < VOCAB) {
                    out[rb0 + col + 1] = d[mi][ni][1];
                    out[rb1 + col + 1] = d[mi][ni][3];
                }
            }
        }
    }
}

// ---------------------------------------------------------------------------
extern "C" void kernel_launch(void* const* d_in, const int* in_sizes, int n_in,
                              void* d_out, int out_size)
{
    const float* hidden = (const float*)d_in[0];
    const int*   tids   = (const int*)  d_in[1];
    const float* ip_w   = (const float*)d_in[2];
    const float* ip_b   = (const float*)d_in[3];
    const float* w_ih0  = (const float*)d_in[4];
    const float* w_hh0  = (const float*)d_in[5];
    const float* b_ih0  = (const float*)d_in[6];
    const float* b_hh0  = (const float*)d_in[7];
    const float* w_ih1  = (const float*)d_in[8];
    const float* w_hh1  = (const float*)d_in[9];
    const float* b_ih1  = (const float*)d_in[10];
    const float* b_hh1  = (const float*)d_in[11];
    const float* embed  = (const float*)d_in[12];
    const float* out_w  = (const float*)d_in[13];
    float* out = (float*)d_out;

    cudaFuncSetAttribute(logits_mma, cudaFuncAttributeMaxDynamicSharedMemorySize, LOGITS_SMEM);

    gru_fused<<<GRIDN, 512>>>(hidden, tids, ip_w, ip_b,
                              w_ih0, w_hh0, b_ih0, b_hh0,
                              w_ih1, w_hh1, b_ih1, b_hh1, embed);

    logits_mma<<<dim3(2, (VOCAB + 127) / 128), 256, LOGITS_SMEM>>>(out_w, out);
}

// round 11
// speedup vs baseline: 1.3482x; 1.3482x over previous
#include <cuda_runtime.h>
#include <cuda_fp16.h>
#include <math.h>
#include <stdint.h>

// ---------------------------------------------------------------------------
// ReDrafterHead: 2-layer GRU draft head + big vocab projection.
// B=64, HIDDEN=4096, DH=512, VOCAB=50257, NUM_DRAFT=4.
//
// Round 11:
//  - gru: round-9 structure, but utile remapped warp<->col-triple,
//    lane<->rows (l, l+32): W reads become smem broadcasts (free),
//    A reads conflict-free -> FFMA-bound.
//  - logits: round-10 (CTA 128x128, warp 64x32, single fp16, 2 CTAs/SM).
// ---------------------------------------------------------------------------

#define B_      64
#define HID     4096
#define DH      512
#define VOCAB   50257
#define NDRAFT  4
#define GRIDN   128

__device__ float g_h[2][2][B_ * DH];        // [layer][slot][b*DH+j]
__device__ float g_part[16 * B_ * DH];      // ip split-K partials
__device__ __half g_Ah[B_ * NDRAFT * DH];   // h2 rows fp16, m = b*4+step
__device__ unsigned int g_bcount;           // monotonic barrier counter

__device__ __forceinline__ float sigmoidf_(float v) { return 1.0f / (1.0f + __expf(-v)); }

__device__ __forceinline__ uint32_t pack_f16x2(__half lo, __half hi) {
    return ((uint32_t)__half_as_ushort(hi) << 16) | (uint32_t)__half_as_ushort(lo);
}
__device__ __forceinline__ uint32_t smem_to_u32(const void* p) {
    uint32_t a;
    asm("{ .reg .u64 t; cvta.to.shared.u64 t, %1; cvt.u32.u64 %0, t; }" : "=r"(a) : "l"(p));
    return a;
}
__device__ __forceinline__ void ldsm4(uint32_t* r, uint32_t addr) {
    asm volatile("ldmatrix.sync.aligned.m8n8.x4.shared.b16 {%0,%1,%2,%3}, [%4];"
        : "=r"(r[0]), "=r"(r[1]), "=r"(r[2]), "=r"(r[3]) : "r"(addr));
}
__device__ __forceinline__ void mma16816h(float* d, const uint32_t* a, const uint32_t* b) {
    asm volatile("mma.sync.aligned.m16n8k16.row.col.f32.f16.f16.f32 "
        "{%0,%1,%2,%3}, {%4,%5,%6,%7}, {%8,%9}, {%0,%1,%2,%3};"
        : "+f"(d[0]), "+f"(d[1]), "+f"(d[2]), "+f"(d[3])
        : "r"(a[0]), "r"(a[1]), "r"(a[2]), "r"(a[3]), "r"(b[0]), "r"(b[1]));
}

// Grid-wide barrier: monotonic counter (graph-replay safe; GRIDN co-resident).
__device__ __forceinline__ void grid_barrier(int tid) {
    __syncthreads();
    if (tid == 0) {
        __threadfence();
        unsigned int old = atomicAdd(&g_bcount, 1u);
        unsigned int target = (old / GRIDN + 1u) * GRIDN;
        unsigned int v;
        do {
            asm volatile("ld.acquire.gpu.global.u32 %0, [%1];" : "=r"(v) : "l"(&g_bcount));
        } while (v < target);
    }
    __syncthreads();
}

// ---------------------------------------------------------------------------
struct SmemIP { float As[32][64]; float Ws[32][64]; };
struct SmemG  { float A1[64][36]; float padA[4]; float A2[64][36];
                float W[24][36];  float epi[64][25]; };

// One GRU layer for one step. CTA owns j-range [jb, jb+4): GEMM 64 x 24 x 512
// (cols 0-11: gi {r,z,n} x 4j via Wih & A1; 12-23: gh via Whh & A2) + combine.
// utile: warp w -> cols 3w..3w+2 (W reads are warp-uniform broadcasts);
//        lane l -> rows l and l+32 (stride-36 rows -> conflict-free banks).
// a1mode: 0 = zeros, 1 = embed gather, 2 = pointer.
__device__ __forceinline__ void gates_layer(
    SmemG& s, const int* sTid, int tid, int jb,
    int a1mode, const float* A1g, const float* A2g, const float* embed,
    const float* Wih, const float* Whh,
    const float* bih, const float* bhh,
    const float* hOld, float* hNew,
    bool writeA, int step)
{
    const int lane = tid & 31;
    const int wrp  = tid >> 5;             // 0..7
    const int c0   = wrp * 3;              // 0..21
    const float* As = (wrp < 4) ? &s.A1[0][0] : &s.A2[0][0];
    float acc[2][3] = {};

    // loader indices (unchanged from round 9): one float4 per array per tile
    float4 pA1[2], pA2[2], pW;
    const int frow = tid >> 3;             // 0..31 (+32)
    const int fc4  = (tid & 7) * 4;        // 0..28
    const int wr   = tid >> 3;             // W row when tid < 192
    const int wrr  = (wr < 12) ? wr : wr - 12;
    const float* wbase = (wr < 12) ? Wih : Whh;
    const long  woff = (long)((wrr >> 2) * 512 + jb + (wrr & 3)) * DH + fc4;

    auto fetch = [&](int kt) {
        #pragma unroll
        for (int i = 0; i < 2; i++) {
            int row = frow + i * 32;
            if (a1mode == 0)      pA1[i] = make_float4(0.f, 0.f, 0.f, 0.f);
            else if (a1mode == 1) pA1[i] = *reinterpret_cast<const float4*>(
                                             &embed[(long)sTid[row] * DH + kt + fc4]);
            else                  pA1[i] = *reinterpret_cast<const float4*>(
                                             &A1g[row * DH + kt + fc4]);
            pA2[i] = *reinterpret_cast<const float4*>(&A2g[row * DH + kt + fc4]);
        }
        if (tid < 192)
            pW = *reinterpret_cast<const float4*>(&wbase[woff + kt]);
    };
    auto stage = [&]() {
        #pragma unroll
        for (int i = 0; i < 2; i++) {
            int row = frow + i * 32;
            *reinterpret_cast<float4*>(&s.A1[row][fc4]) = pA1[i];
            *reinterpret_cast<float4*>(&s.A2[row][fc4]) = pA2[i];
        }
        if (tid < 192)
            *reinterpret_cast<float4*>(&s.W[wr][fc4]) = pW;
    };

    fetch(0);
    for (int kt = 0; kt < DH; kt += 32) {
        __syncthreads();
        stage();
        __syncthreads();
        if (kt + 32 < DH) fetch(kt + 32);
        #pragma unroll
        for (int k = 0; k < 32; k += 4) {
            float4 w0 = *reinterpret_cast<const float4*>(&s.W[c0 + 0][k]);  // broadcast
            float4 w1 = *reinterpret_cast<const float4*>(&s.W[c0 + 1][k]);  // broadcast
            float4 w2 = *reinterpret_cast<const float4*>(&s.W[c0 + 2][k]);  // broadcast
            float4 a0 = *reinterpret_cast<const float4*>(&As[lane * 36 + k]);
            float4 a1 = *reinterpret_cast<const float4*>(&As[(lane + 32) * 36 + k]);
            acc[0][0] += a0.x * w0.x + a0.y * w0.y + a0.z * w0.z + a0.w * w0.w;
            acc[0][1] += a0.x * w1.x + a0.y * w1.y + a0.z * w1.z + a0.w * w1.w;
            acc[0][2] += a0.x * w2.x + a0.y * w2.y + a0.z * w2.z + a0.w * w2.w;
            acc[1][0] += a1.x * w0.x + a1.y * w0.y + a1.z * w0.z + a1.w * w0.w;
            acc[1][1] += a1.x * w1.x + a1.y * w1.y + a1.z * w1.z + a1.w * w1.w;
            acc[1][2] += a1.x * w2.x + a1.y * w2.y + a1.z * w2.z + a1.w * w2.w;
        }
    }

    #pragma unroll
    for (int cc = 0; cc < 3; cc++) {
        s.epi[lane][c0 + cc]      = acc[0][cc];
        s.epi[lane + 32][c0 + cc] = acc[1][cc];
    }
    __syncthreads();
    {
        int m = tid >> 2, j = tid & 3, jj = jb + j;
        const float* E = &s.epi[m][0];
        // col cx in 0..23 maps to W row cx: gate = cx>>2 (within half), j = cx&3
        float r = sigmoidf_(E[j]       + bih[jj]        + E[12 + j] + bhh[jj]);
        float z = sigmoidf_(E[4 + j]   + bih[512 + jj]  + E[16 + j] + bhh[512 + jj]);
        float n = tanhf(E[8 + j] + bih[1024 + jj] + r * (E[20 + j] + bhh[1024 + jj]));
        float hnew = (1.f - z) * n + z * hOld[m * DH + jj];
        hNew[m * DH + jj] = hnew;
        if (writeA)
            g_Ah[(m * NDRAFT + step) * DH + jj] = __float2half(hnew);
    }
}

// ---------------------------------------------------------------------------
__global__ __launch_bounds__(256) void gru_fused(
    const float* __restrict__ hidden, const int* __restrict__ tids,
    const float* __restrict__ ip_w,  const float* __restrict__ ip_b,
    const float* __restrict__ w_ih0, const float* __restrict__ w_hh0,
    const float* __restrict__ b_ih0, const float* __restrict__ b_hh0,
    const float* __restrict__ w_ih1, const float* __restrict__ w_hh1,
    const float* __restrict__ b_ih1, const float* __restrict__ b_hh1,
    const float* __restrict__ embed)
{
    __shared__ union { SmemIP ip; SmemG g; } sm;
    __shared__ int sTid[64];
    const int tid = threadIdx.x;
    const int c = blockIdx.x;

    // ---- phase 0: input projection partials (64x64 n-tile, 256-k slice) ----
    {
        const int n0 = (c & 7) * 64;
        const int kbase = (c >> 3) * 256;
        const int ty = tid >> 4, tx = tid & 15;
        float acc[4][4] = {};
        for (int kt = 0; kt < 256; kt += 32) {
            #pragma unroll
            for (int i = 0; i < 2; i++) {
                int f = tid + i * 256;
                int m = f >> 3;
                int kq = (f & 7) << 2;
                float4 va = *reinterpret_cast<const float4*>(&hidden[m * HID + kbase + kt + kq]);
                sm.ip.As[kq + 0][m] = va.x; sm.ip.As[kq + 1][m] = va.y;
                sm.ip.As[kq + 2][m] = va.z; sm.ip.As[kq + 3][m] = va.w;
                float4 vw = *reinterpret_cast<const float4*>(&ip_w[(n0 + m) * HID + kbase + kt + kq]);
                sm.ip.Ws[kq + 0][m] = vw.x; sm.ip.Ws[kq + 1][m] = vw.y;
                sm.ip.Ws[kq + 2][m] = vw.z; sm.ip.Ws[kq + 3][m] = vw.w;
            }
            __syncthreads();
            #pragma unroll
            for (int kk = 0; kk < 32; kk++) {
                float a[4], b[4];
                #pragma unroll
                for (int i = 0; i < 4; i++) { a[i] = sm.ip.As[kk][ty * 4 + i]; b[i] = sm.ip.Ws[kk][tx * 4 + i]; }
                #pragma unroll
                for (int i = 0; i < 4; i++)
                    #pragma unroll
                    for (int j = 0; j < 4; j++) acc[i][j] += a[i] * b[j];
            }
            __syncthreads();
        }
        float* part = g_part + (c >> 3) * (B_ * DH);
        #pragma unroll
        for (int i = 0; i < 4; i++)
            #pragma unroll
            for (int j = 0; j < 4; j++)
                part[(ty * 4 + i) * DH + n0 + tx * 4 + j] = acc[i][j];
    }
    grid_barrier(tid);

    // ---- phase 1: reduce 16 partials + bias ----
    {
        int idx = c * 256 + tid;
        float s = 0.f;
        #pragma unroll
        for (int p = 0; p < 16; p++) s += g_part[p * (B_ * DH) + idx];
        s += ip_b[idx & (DH - 1)];
        g_h[0][0][idx] = s;
        g_h[1][0][idx] = s;
    }
    grid_barrier(tid);

    // ---- 4 draft steps x 2 GRU layers ----
    const int jb = c * 4;
    for (int step = 0; step < NDRAFT; step++) {
        const int p = step & 1;
        if (step > 0 && tid < 64) sTid[tid] = tids[tid * NDRAFT + step - 1];
        __syncthreads();
        gates_layer(sm.g, sTid, tid, jb,
                    (step == 0) ? 0 : 1, nullptr, g_h[0][p], embed,
                    w_ih0, w_hh0, b_ih0, b_hh0,
                    g_h[0][p], g_h[0][1 - p], false, step);
        grid_barrier(tid);
        gates_layer(sm.g, sTid, tid, jb,
                    2, g_h[0][1 - p], g_h[1][p], embed,
                    w_ih1, w_hh1, b_ih1, b_hh1,
                    g_h[1][p], g_h[1][1 - p], true, step);
        grid_barrier(tid);
    }
}

// ---------------------------------------------------------------------------
// Logits GEMM via single fp16 mma.sync (fp32 accum).
// CTA tile 128(M) x 128(N) x 32(K); 8 warps (2 M x 4 N); warp tile 64x32.
// smem 40KB -> 2 CTAs/SM. grid (2, 393): m-half pairs share B via L2.
// ---------------------------------------------------------------------------
#define ROWB 80
#define AH_OFF(s) ((s) * 10240)
#define BH_OFF(s) (20480 + (s) * 10240)
#define LOGITS_SMEM 40960

__global__ __launch_bounds__(256, 2) void logits_mma(const float* __restrict__ W,
                                                     float* __restrict__ out)
{
    extern __shared__ char smem[];
    const uint32_t sbase = smem_to_u32(smem);
    const int tid  = threadIdx.x;
    const int lane = tid & 31;
    const int w    = tid >> 5;
    const int wm   = w >> 2;   // 0..1
    const int wn   = w & 3;    // 0..3
    const int m0   = blockIdx.x * 128;
    const int n0   = blockIdx.y * 128;

    float d[4][4][4];
    #pragma unroll
    for (int i = 0; i < 4; i++)
        #pragma unroll
        for (int j = 0; j < 4; j++)
            #pragma unroll
            for (int q = 0; q < 4; q++) d[i][j][q] = 0.f;

    float4 breg[4];

    auto cpasync_A = [&](int c, int s) {
        const int k0 = c * 32;
        #pragma unroll
        for (int i = 0; i < 2; i++) {
            int idx = tid + i * 256;         // 0..511
            int row = idx >> 2;              // 0..127
            int ch  = idx & 3;               // 16B chunk (8 halves)
            const __half* sh = &g_Ah[(m0 + row) * DH + k0 + ch * 8];
            uint32_t dh = sbase + AH_OFF(s) + row * ROWB + ch * 16;
            asm volatile("cp.async.ca.shared.global [%0], [%1], 16;" :: "r"(dh), "l"(sh));
        }
        asm volatile("cp.async.commit_group;" ::: "memory");
    };

    auto ldg_B = [&](int c) {
        const int k0 = c * 32;
        #pragma unroll
        for (int i = 0; i < 4; i++) {
            int idx = tid + i * 256;         // 0..1023
            int row = idx >> 3;              // 0..127
            int col = (idx & 7) * 4;
            int vr = n0 + row;
            breg[i] = (vr < VOCAB)
                ? *reinterpret_cast<const float4*>(&W[(long)vr * DH + k0 + col])
                : make_float4(0.f, 0.f, 0.f, 0.f);
        }
    };

    auto sts_B = [&](int s) {
        #pragma unroll
        for (int i = 0; i < 4; i++) {
            int idx = tid + i * 256;
            int row = idx >> 3;
            int col = (idx & 7) * 4;
            float4 v = breg[i];
            uint2 ph;
            ph.x = pack_f16x2(__float2half(v.x), __float2half(v.y));
            ph.y = pack_f16x2(__float2half(v.z), __float2half(v.w));
            *reinterpret_cast<uint2*>(smem + BH_OFF(s) + row * ROWB + col * 2) = ph;
        }
    };

    auto compute = [&](int s) {
        #pragma unroll
        for (int ks = 0; ks < 2; ks++) {
            uint32_t ah[4][4];
            #pragma unroll
            for (int mi = 0; mi < 4; mi++) {
                int row = wm * 64 + mi * 16 + (lane & 15);
                int kc  = ks * 32 + (lane >> 4) * 16;
                ldsm4(ah[mi], sbase + AH_OFF(s) + row * ROWB + kc);
            }
            uint32_t bh[4][2];
            #pragma unroll
            for (int nb = 0; nb < 2; nb++) {
                int gq  = lane >> 3;
                int row = wn * 32 + nb * 16 + (gq >> 1) * 8 + (lane & 7);
                int kc  = ks * 32 + (gq & 1) * 16;
                ldsm4(&bh[nb * 2][0], sbase + BH_OFF(s) + row * ROWB + kc);
            }
            #pragma unroll
            for (int mi = 0; mi < 4; mi++)
                #pragma unroll
                for (int ni = 0; ni < 4; ni++)
                    mma16816h(d[mi][ni], ah[mi], bh[ni]);
        }
    };

    cpasync_A(0, 0);
    ldg_B(0);
    sts_B(0);
    asm volatile("cp.async.wait_group 0;" ::: "memory");
    __syncthreads();

    #pragma unroll 1
    for (int c = 0; c < 16; c++) {
        int s = c & 1;
        if (c + 1 < 16) {
            cpasync_A(c + 1, 1 - s);
            ldg_B(c + 1);
        }
        compute(s);
        if (c + 1 < 16) {
            sts_B(1 - s);
            asm volatile("cp.async.wait_group 0;" ::: "memory");
        }
        __syncthreads();
    }

    const int g  = lane >> 2;
    const int i2 = (lane & 3) * 2;
    #pragma unroll
    for (int mi = 0; mi < 4; mi++) {
        int r0 = m0 + wm * 64 + mi * 16 + g;
        long rb0 = (long)r0 * VOCAB;
        long rb1 = (long)(r0 + 8) * VOCAB;
        #pragma unroll
        for (int ni = 0; ni < 4; ni++) {
            int col = n0 + wn * 32 + ni * 8 + i2;
            if (col < VOCAB) {
                out[rb0 + col] = d[mi][ni][0];
                out[rb1 + col] = d[mi][ni][2];
                if (col + 1 < VOCAB) {
                    out[rb0 + col + 1] = d[mi][ni][1];
                    out[rb1 + col + 1] = d[mi][ni][3];
                }
            }
        }
    }
}

// ---------------------------------------------------------------------------
extern "C" void kernel_launch(void* const* d_in, const int* in_sizes, int n_in,
                              void* d_out, int out_size)
{
    const float* hidden = (const float*)d_in[0];
    const int*   tids   = (const int*)  d_in[1];
    const float* ip_w   = (const float*)d_in[2];
    const float* ip_b   = (const float*)d_in[3];
    const float* w_ih0  = (const float*)d_in[4];
    const float* w_hh0  = (const float*)d_in[5];
    const float* b_ih0  = (const float*)d_in[6];
    const float* b_hh0  = (const float*)d_in[7];
    const float* w_ih1  = (const float*)d_in[8];
    const float* w_hh1  = (const float*)d_in[9];
    const float* b_ih1  = (const float*)d_in[10];
    const float* b_hh1  = (const float*)d_in[11];
    const float* embed  = (const float*)d_in[12];
    const float* out_w  = (const float*)d_in[13];
    float* out = (float*)d_out;

    cudaFuncSetAttribute(logits_mma, cudaFuncAttributeMaxDynamicSharedMemorySize, LOGITS_SMEM);

    gru_fused<<<GRIDN, 256>>>(hidden, tids, ip_w, ip_b,
                              w_ih0, w_hh0, b_ih0, b_hh0,
                              w_ih1, w_hh1, b_ih1, b_hh1, embed);

    logits_mma<<<dim3(2, (VOCAB + 127) / 128), 256, LOGITS_SMEM>>>(out_w, out);
}

// round 12
// speedup vs baseline: 1.5875x; 1.1776x over previous
#include <cuda_runtime.h>
#include <cuda_fp16.h>
#include <math.h>
#include <stdint.h>

// ---------------------------------------------------------------------------
// ReDrafterHead: 2-layer GRU draft head + big vocab projection.
// B=64, HIDDEN=4096, DH=512, VOCAB=50257, NUM_DRAFT=4.
//
// Round 12:
//  - GRU gate GEMMs moved to HMMA (mma.sync m16n8k16): gi/gh CTA split,
//    CTA tile 64x24(pad 32)x512, A as fp16 hi/lo (2-term, exact-ish),
//    W single fp16 (pre-converted). Gates staged in global; combine phase
//    fused into same persistent kernel.
//  - logits: unchanged single-fp16 HMMA (CTA 128x128, 2 CTAs/SM).
// ---------------------------------------------------------------------------

#define B_      64
#define HID     4096
#define DH      512
#define VOCAB   50257
#define NDRAFT  4
#define GRIDN   128
#define G3      1536

__device__ float  g_h0[B_ * DH];
__device__ float  g_h1[B_ * DH];
__device__ __half g_h0h[B_ * DH], g_h0l[B_ * DH];
__device__ __half g_h1h[B_ * DH], g_h1l[B_ * DH];
__device__ __half g_xh[B_ * DH],  g_xl[B_ * DH];
__device__ float  g_gates[B_ * 3072];       // [m][gi r,z,n | gh r,z,n] x 512
__device__ float  g_part[16 * B_ * DH];     // ip split-K partials
__device__ __half g_Ah[B_ * NDRAFT * DH];   // logits A fp16, m = b*4+step
__device__ __half g_wih0h[G3 * DH], g_whh0h[G3 * DH];
__device__ __half g_wih1h[G3 * DH], g_whh1h[G3 * DH];
__device__ unsigned int g_bcount;           // monotonic barrier counter

__device__ __forceinline__ float sigmoidf_(float v) { return 1.0f / (1.0f + __expf(-v)); }

__device__ __forceinline__ uint32_t pack_f16x2(__half lo, __half hi) {
    return ((uint32_t)__half_as_ushort(hi) << 16) | (uint32_t)__half_as_ushort(lo);
}
__device__ __forceinline__ uint32_t smem_to_u32(const void* p) {
    uint32_t a;
    asm("{ .reg .u64 t; cvta.to.shared.u64 t, %1; cvt.u32.u64 %0, t; }" : "=r"(a) : "l"(p));
    return a;
}
__device__ __forceinline__ void ldsm4(uint32_t* r, uint32_t addr) {
    asm volatile("ldmatrix.sync.aligned.m8n8.x4.shared.b16 {%0,%1,%2,%3}, [%4];"
        : "=r"(r[0]), "=r"(r[1]), "=r"(r[2]), "=r"(r[3]) : "r"(addr));
}
__device__ __forceinline__ void mma16816h(float* d, const uint32_t* a, const uint32_t* b) {
    asm volatile("mma.sync.aligned.m16n8k16.row.col.f32.f16.f16.f32 "
        "{%0,%1,%2,%3}, {%4,%5,%6,%7}, {%8,%9}, {%0,%1,%2,%3};"
        : "+f"(d[0]), "+f"(d[1]), "+f"(d[2]), "+f"(d[3])
        : "r"(a[0]), "r"(a[1]), "r"(a[2]), "r"(a[3]), "r"(b[0]), "r"(b[1]));
}

// Grid-wide barrier: monotonic counter (graph-replay safe; GRIDN co-resident).
__device__ __forceinline__ void grid_barrier(int tid) {
    __syncthreads();
    if (tid == 0) {
        __threadfence();
        unsigned int old = atomicAdd(&g_bcount, 1u);
        unsigned int target = (old / GRIDN + 1u) * GRIDN;
        unsigned int v;
        do {
            asm volatile("ld.acquire.gpu.global.u32 %0, [%1];" : "=r"(v) : "l"(&g_bcount));
        } while (v < target);
    }
    __syncthreads();
}

// ---------------------------------------------------------------------------
struct SmemIP { float As[32][64]; float Ws[32][64]; };
// Gates HMMA stage buffers: 80B rows (16B-aligned, 5*16B -> conflict-free ldsm)
struct SmemGa { __half Ahi[2][64][40]; __half Alo[2][64][40]; __half W[2][32][40]; };
// offsets: Ahi 0 (stage stride 5120), Alo 20480... compute in code via constants:
#define GA_AHI(st) ((st) * 5120)
#define GA_ALO(st) (10240 + (st) * 5120)
#define GA_W(st)   (20480 + (st) * 2560)

// ---------------------------------------------------------------------------
// Gates GEMM via HMMA: C[64 x 24] = A[64 x 512] * W[24 x 512]^T  (N padded 32)
// A = (Ahi + Alo) fp16 2-term; W fp16 single.
// 8 warps: wm = w>>2 (m32 half), wn = w&3 (n8 tile; wn==3 = padding, no store)
// Output gate g (=wn) cols -> g_gates[m][ghOff + g*512 + jr + jj].
// ---------------------------------------------------------------------------
__device__ __forceinline__ void gates_mma(
    SmemGa& s, int tid, int jr, int ghOff,
    const __half* __restrict__ Ahi, const __half* __restrict__ Alo,
    const __half* __restrict__ Wg)
{
    const uint32_t sb = smem_to_u32(&s);
    const int lane = tid & 31;
    const int w  = tid >> 5;
    const int wm = w >> 2;     // 0..1
    const int wn = w & 3;      // 0..3
    const int ng = wn >> 1;    // n16 group
    const int p  = wn & 1;     // n8 within group
    const int gq = lane >> 3;

    float d[2][4] = {};

    // loader indices
    const int arow = tid >> 2;             // 0..63
    const int ach  = tid & 3;              // 16B chunk
    int gidx = 0;
    if (tid < 128) {
        int r = tid >> 2;                  // 0..31
        int gate = (r < 24) ? (r >> 3) : 0;
        int jj   = (r < 24) ? (r & 7) : (r - 24);
        gidx = gate * 512 + jr + jj;
    }

    auto load_tile = [&](int t, int st) {
        const int k0 = t * 32;
        uint32_t da = sb + GA_AHI(st) + arow * 80 + ach * 16;
        const __half* sa = &Ahi[arow * DH + k0 + ach * 8];
        asm volatile("cp.async.ca.shared.global [%0], [%1], 16;" :: "r"(da), "l"(sa));
        uint32_t dl = sb + GA_ALO(st) + arow * 80 + ach * 16;
        const __half* sl = &Alo[arow * DH + k0 + ach * 8];
        asm volatile("cp.async.ca.shared.global [%0], [%1], 16;" :: "r"(dl), "l"(sl));
        if (tid < 128) {
            uint32_t dw = sb + GA_W(st) + (tid >> 2) * 80 + (tid & 3) * 16;
            const __half* sw = &Wg[(long)gidx * DH + k0 + (tid & 3) * 8];
            asm volatile("cp.async.ca.shared.global [%0], [%1], 16;" :: "r"(dw), "l"(sw));
        }
        asm volatile("cp.async.commit_group;" ::: "memory");
    };

    auto compute = [&](int st) {
        #pragma unroll
        for (int ks = 0; ks < 2; ks++) {
            uint32_t ahi2[2][4], alo2[2][4], bt[4];
            #pragma unroll
            for (int mi = 0; mi < 2; mi++) {
                int row = wm * 32 + mi * 16 + (lane & 15);
                int kc  = ks * 32 + (lane >> 4) * 16;
                ldsm4(ahi2[mi], sb + GA_AHI(st) + row * 80 + kc);
                ldsm4(alo2[mi], sb + GA_ALO(st) + row * 80 + kc);
            }
            {
                int rowB = ng * 16 + (gq >> 1) * 8 + (lane & 7);
                int kcB  = ks * 32 + (gq & 1) * 16;
                ldsm4(bt, sb + GA_W(st) + rowB * 80 + kcB);
            }
            uint32_t bf[2] = { bt[2 * p], bt[2 * p + 1] };
            #pragma unroll
            for (int mi = 0; mi < 2; mi++) {
                mma16816h(d[mi], ahi2[mi], bf);
                mma16816h(d[mi], alo2[mi], bf);
            }
        }
    };

    load_tile(0, 0);
    asm volatile("cp.async.wait_group 0;" ::: "memory");
    __syncthreads();

    #pragma unroll 1
    for (int t = 0; t < 16; t++) {
        const int st = t & 1;
        if (t + 1 < 16) load_tile(t + 1, 1 - st);
        compute(st);
        if (t + 1 < 16)
            asm volatile("cp.async.wait_group 0;" ::: "memory");
        __syncthreads();
    }

    // epilogue: store gate columns (skip wn==3 padding)
    if (wn < 3) {
        const int colb = ghOff + wn * 512 + jr + (lane & 3) * 2;
        #pragma unroll
        for (int mi = 0; mi < 2; mi++) {
            int r = wm * 32 + mi * 16 + (lane >> 2);
            float* gr = g_gates + r * 3072;
            gr[colb]     = d[mi][0];
            gr[colb + 1] = d[mi][1];
            gr += 8 * 3072;
            gr[colb]     = d[mi][2];
            gr[colb + 1] = d[mi][3];
        }
    }
}

// combine: one (m, j) per thread (32768 threads exactly).
__device__ __forceinline__ void gru_combine_ph(
    int c, int tid, const float* __restrict__ bih, const float* __restrict__ bhh,
    float* __restrict__ h, __half* __restrict__ hh, __half* __restrict__ hl,
    bool isL1, int step,
    const int* __restrict__ tids, const float* __restrict__ embed)
{
    int idx = c * 256 + tid;
    int m = idx >> 9, j = idx & 511;
    const float* G = g_gates + m * 3072;
    float r = sigmoidf_(G[j]        + bih[j]        + G[1536 + j] + bhh[j]);
    float z = sigmoidf_(G[512 + j]  + bih[512 + j]  + G[2048 + j] + bhh[512 + j]);
    float n = tanhf(G[1024 + j] + bih[1024 + j] + r * (G[2560 + j] + bhh[1024 + j]));
    float hn = (1.f - z) * n + z * h[idx];
    h[idx] = hn;
    __half hi = __float2half(hn);
    hh[idx] = hi;
    hl[idx] = __float2half(hn - __half2float(hi));
    if (isL1) {
        g_Ah[(m * NDRAFT + step) * DH + j] = hi;
        if (step < NDRAFT - 1) {
            float xv = embed[(long)tids[m * NDRAFT + step] * DH + j];
            __half xh = __float2half(xv);
            g_xh[idx] = xh;
            g_xl[idx] = __float2half(xv - __half2float(xh));
        }
    }
}

// ---------------------------------------------------------------------------
__global__ __launch_bounds__(256) void gru_fused(
    const float* __restrict__ hidden, const int* __restrict__ tids,
    const float* __restrict__ ip_w,  const float* __restrict__ ip_b,
    const float* __restrict__ w_ih0, const float* __restrict__ w_hh0,
    const float* __restrict__ b_ih0, const float* __restrict__ b_hh0,
    const float* __restrict__ w_ih1, const float* __restrict__ w_hh1,
    const float* __restrict__ b_ih1, const float* __restrict__ b_hh1,
    const float* __restrict__ embed)
{
    __shared__ union { SmemIP ip; SmemGa g; } sm;
    const int tid = threadIdx.x;
    const int c = blockIdx.x;

    // ---- phase -1: convert GRU weights to fp16 (once per call) ----
    for (int i = c * 256 + tid; i < G3 * DH; i += GRIDN * 256) {
        g_wih0h[i] = __float2half(w_ih0[i]);
        g_whh0h[i] = __float2half(w_hh0[i]);
        g_wih1h[i] = __float2half(w_ih1[i]);
        g_whh1h[i] = __float2half(w_hh1[i]);
    }

    // ---- phase 0: input projection partials (64x64 n-tile, 256-k slice) ----
    {
        const int n0 = (c & 7) * 64;
        const int kbase = (c >> 3) * 256;
        const int ty = tid >> 4, tx = tid & 15;
        float acc[4][4] = {};
        for (int kt = 0; kt < 256; kt += 32) {
            #pragma unroll
            for (int i = 0; i < 2; i++) {
                int f = tid + i * 256;
                int m = f >> 3;
                int kq = (f & 7) << 2;
                float4 va = *reinterpret_cast<const float4*>(&hidden[m * HID + kbase + kt + kq]);
                sm.ip.As[kq + 0][m] = va.x; sm.ip.As[kq + 1][m] = va.y;
                sm.ip.As[kq + 2][m] = va.z; sm.ip.As[kq + 3][m] = va.w;
                float4 vw = *reinterpret_cast<const float4*>(&ip_w[(n0 + m) * HID + kbase + kt + kq]);
                sm.ip.Ws[kq + 0][m] = vw.x; sm.ip.Ws[kq + 1][m] = vw.y;
                sm.ip.Ws[kq + 2][m] = vw.z; sm.ip.Ws[kq + 3][m] = vw.w;
            }
            __syncthreads();
            #pragma unroll
            for (int kk = 0; kk < 32; kk++) {
                float a[4], b[4];
                #pragma unroll
                for (int i = 0; i < 4; i++) { a[i] = sm.ip.As[kk][ty * 4 + i]; b[i] = sm.ip.Ws[kk][tx * 4 + i]; }
                #pragma unroll
                for (int i = 0; i < 4; i++)
                    #pragma unroll
                    for (int j = 0; j < 4; j++) acc[i][j] += a[i] * b[j];
            }
            __syncthreads();
        }
        float* part = g_part + (c >> 3) * (B_ * DH);
        #pragma unroll
        for (int i = 0; i < 4; i++)
            #pragma unroll
            for (int j = 0; j < 4; j++)
                part[(ty * 4 + i) * DH + n0 + tx * 4 + j] = acc[i][j];
    }
    grid_barrier(tid);

    // ---- phase 1: reduce 16 partials + bias; init fp16 copies + x = 0 ----
    {
        int idx = c * 256 + tid;
        float s = 0.f;
        #pragma unroll
        for (int p = 0; p < 16; p++) s += g_part[p * (B_ * DH) + idx];
        s += ip_b[idx & (DH - 1)];
        g_h0[idx] = s;
        g_h1[idx] = s;
        __half hi = __float2half(s);
        __half lo = __float2half(s - __half2float(hi));
        g_h0h[idx] = hi; g_h0l[idx] = lo;
        g_h1h[idx] = hi; g_h1l[idx] = lo;
        g_xh[idx] = __float2half(0.f);
        g_xl[idx] = __float2half(0.f);
    }
    grid_barrier(tid);

    // ---- 4 draft steps x 2 GRU layers; CTA is a gi- or gh-worker ----
    const bool isGH = (c >= 64);
    const int  jr   = (c & 63) * 8;
    const int  ghOff = isGH ? 1536 : 0;

    for (int step = 0; step < NDRAFT; step++) {
        // layer 0: gi = x @ w_ih0^T | gh = h0 @ w_hh0^T
        gates_mma(sm.g, tid, jr, ghOff,
                  isGH ? g_h0h : g_xh, isGH ? g_h0l : g_xl,
                  isGH ? g_whh0h : g_wih0h);
        grid_barrier(tid);
        gru_combine_ph(c, tid, b_ih0, b_hh0, g_h0, g_h0h, g_h0l, false, step, tids, embed);
        grid_barrier(tid);
        // layer 1: gi = h0_new @ w_ih1^T | gh = h1 @ w_hh1^T
        gates_mma(sm.g, tid, jr, ghOff,
                  isGH ? g_h1h : g_h0h, isGH ? g_h1l : g_h0l,
                  isGH ? g_whh1h : g_wih1h);
        grid_barrier(tid);
        gru_combine_ph(c, tid, b_ih1, b_hh1, g_h1, g_h1h, g_h1l, true, step, tids, embed);
        grid_barrier(tid);
    }
}

// ---------------------------------------------------------------------------
// Logits GEMM via single fp16 mma.sync (fp32 accum) — round-10/11 proven.
// CTA tile 128(M) x 128(N) x 32(K); 8 warps (2 M x 4 N); warp tile 64x32.
// smem 40KB -> 2 CTAs/SM. grid (2, 393).
// ---------------------------------------------------------------------------
#define ROWB 80
#define AH_OFF(s) ((s) * 10240)
#define BH_OFF(s) (20480 + (s) * 10240)
#define LOGITS_SMEM 40960

__global__ __launch_bounds__(256, 2) void logits_mma(const float* __restrict__ W,
                                                     float* __restrict__ out)
{
    extern __shared__ char smem[];
    const uint32_t sbase = smem_to_u32(smem);
    const int tid  = threadIdx.x;
    const int lane = tid & 31;
    const int w    = tid >> 5;
    const int wm   = w >> 2;
    const int wn   = w & 3;
    const int m0   = blockIdx.x * 128;
    const int n0   = blockIdx.y * 128;

    float d[4][4][4];
    #pragma unroll
    for (int i = 0; i < 4; i++)
        #pragma unroll
        for (int j = 0; j < 4; j++)
            #pragma unroll
            for (int q = 0; q < 4; q++) d[i][j][q] = 0.f;

    float4 breg[4];

    auto cpasync_A = [&](int c, int s) {
        const int k0 = c * 32;
        #pragma unroll
        for (int i = 0; i < 2; i++) {
            int idx = tid + i * 256;
            int row = idx >> 2;
            int ch  = idx & 3;
            const __half* sh = &g_Ah[(m0 + row) * DH + k0 + ch * 8];
            uint32_t dh = sbase + AH_OFF(s) + row * ROWB + ch * 16;
            asm volatile("cp.async.ca.shared.global [%0], [%1], 16;" :: "r"(dh), "l"(sh));
        }
        asm volatile("cp.async.commit_group;" ::: "memory");
    };

    auto ldg_B = [&](int c) {
        const int k0 = c * 32;
        #pragma unroll
        for (int i = 0; i < 4; i++) {
            int idx = tid + i * 256;
            int row = idx >> 3;
            int col = (idx & 7) * 4;
            int vr = n0 + row;
            breg[i] = (vr < VOCAB)
                ? *reinterpret_cast<const float4*>(&W[(long)vr * DH + k0 + col])
                : make_float4(0.f, 0.f, 0.f, 0.f);
        }
    };

    auto sts_B = [&](int s) {
        #pragma unroll
        for (int i = 0; i < 4; i++) {
            int idx = tid + i * 256;
            int row = idx >> 3;
            int col = (idx & 7) * 4;
            float4 v = breg[i];
            uint2 ph;
            ph.x = pack_f16x2(__float2half(v.x), __float2half(v.y));
            ph.y = pack_f16x2(__float2half(v.z), __float2half(v.w));
            *reinterpret_cast<uint2*>(smem + BH_OFF(s) + row * ROWB + col * 2) = ph;
        }
    };

    auto compute = [&](int s) {
        #pragma unroll
        for (int ks = 0; ks < 2; ks++) {
            uint32_t ah[4][4];
            #pragma unroll
            for (int mi = 0; mi < 4; mi++) {
                int row = wm * 64 + mi * 16 + (lane & 15);
                int kc  = ks * 32 + (lane >> 4) * 16;
                ldsm4(ah[mi], sbase + AH_OFF(s) + row * ROWB + kc);
            }
            uint32_t bh[4][2];
            #pragma unroll
            for (int nb = 0; nb < 2; nb++) {
                int gq  = lane >> 3;
                int row = wn * 32 + nb * 16 + (gq >> 1) * 8 + (lane & 7);
                int kc  = ks * 32 + (gq & 1) * 16;
                ldsm4(&bh[nb * 2][0], sbase + BH_OFF(s) + row * ROWB + kc);
            }
            #pragma unroll
            for (int mi = 0; mi < 4; mi++)
                #pragma unroll
                for (int ni = 0; ni < 4; ni++)
                    mma16816h(d[mi][ni], ah[mi], bh[ni]);
        }
    };

    cpasync_A(0, 0);
    ldg_B(0);
    sts_B(0);
    asm volatile("cp.async.wait_group 0;" ::: "memory");
    __syncthreads();

    #pragma unroll 1
    for (int c = 0; c < 16; c++) {
        int s = c & 1;
        if (c + 1 < 16) {
            cpasync_A(c + 1, 1 - s);
            ldg_B(c + 1);
        }
        compute(s);
        if (c + 1 < 16) {
            sts_B(1 - s);
            asm volatile("cp.async.wait_group 0;" ::: "memory");
        }
        __syncthreads();
    }

    const int g  = lane >> 2;
    const int i2 = (lane & 3) * 2;
    #pragma unroll
    for (int mi = 0; mi < 4; mi++) {
        int r0 = m0 + wm * 64 + mi * 16 + g;
        long rb0 = (long)r0 * VOCAB;
        long rb1 = (long)(r0 + 8) * VOCAB;
        #pragma unroll
        for (int ni = 0; ni < 4; ni++) {
            int col = n0 + wn * 32 + ni * 8 + i2;
            if (col < VOCAB) {
                out[rb0 + col] = d[mi][ni][0];
                out[rb1 + col] = d[mi][ni][2];
                if (col + 1 < VOCAB) {
                    out[rb0 + col + 1] = d[mi][ni][1];
                    out[rb1 + col + 1] = d[mi][ni][3];
                }
            }
        }
    }
}

// ---------------------------------------------------------------------------
extern "C" void kernel_launch(void* const* d_in, const int* in_sizes, int n_in,
                              void* d_out, int out_size)
{
    const float* hidden = (const float*)d_in[0];
    const int*   tids   = (const int*)  d_in[1];
    const float* ip_w   = (const float*)d_in[2];
    const float* ip_b   = (const float*)d_in[3];
    const float* w_ih0  = (const float*)d_in[4];
    const float* w_hh0  = (const float*)d_in[5];
    const float* b_ih0  = (const float*)d_in[6];
    const float* b_hh0  = (const float*)d_in[7];
    const float* w_ih1  = (const float*)d_in[8];
    const float* w_hh1  = (const float*)d_in[9];
    const float* b_ih1  = (const float*)d_in[10];
    const float* b_hh1  = (const float*)d_in[11];
    const float* embed  = (const float*)d_in[12];
    const float* out_w  = (const float*)d_in[13];
    float* out = (float*)d_out;

    cudaFuncSetAttribute(logits_mma, cudaFuncAttributeMaxDynamicSharedMemorySize, LOGITS_SMEM);

    gru_fused<<<GRIDN, 256>>>(hidden, tids, ip_w, ip_b,
                              w_ih0, w_hh0, b_ih0, b_hh0,
                              w_ih1, w_hh1, b_ih1, b_hh1, embed);

    logits_mma<<<dim3(2, (VOCAB + 127) / 128), 256, LOGITS_SMEM>>>(out_w, out);
}